// round 2
// baseline (speedup 1.0000x reference)
#include <cuda_runtime.h>
#include <cuda_bf16.h>
#include <math.h>

#define MAXN   100000
#define MAXNP  (MAXN + 16)      // padded rows for blocked mm
#define FDIM   44
#define F2DIM  88
#define FEATD  1019
#define MAXG   1024
#define MAXE   1000000

// ---------------- scratch (allocation-free rule: __device__ globals) ----------------
__device__ __align__(256) float g_bufA[MAXNP * F2DIM];   // t = act(h)@W
__device__ __align__(256) float g_bufB[MAXNP * F2DIM];   // aggregated output
__device__ __align__(256) float g_dinv[MAXN];
__device__ __align__(256) int   g_indeg[MAXN];
__device__ __align__(256) int   g_cursor[MAXN];
__device__ __align__(256) int   g_off[MAXN + 1];
__device__ __align__(256) int   g_csrc[MAXE];
__device__ __align__(256) float g_cnorm[MAXE];
__device__ __align__(256) int   g_start[MAXG];
__device__ __align__(256) float g_pool[MAXG * FDIM];

// ---------------- f32x2 packed math helpers ----------------
__device__ __forceinline__ unsigned long long ffma2(unsigned long long a,
                                                    unsigned long long b,
                                                    unsigned long long c) {
    unsigned long long d;
    asm("fma.rn.f32x2 %0, %1, %2, %3;" : "=l"(d) : "l"(a), "l"(b), "l"(c));
    return d;
}
__device__ __forceinline__ unsigned long long splat2(float x) {
    unsigned long long d;
    asm("mov.b64 %0, {%1, %2};" : "=l"(d) : "r"(__float_as_uint(x)), "r"(__float_as_uint(x)));
    return d;
}

// ---------------- degree / norm ----------------
__global__ void k_count(const int* __restrict__ dst, int* __restrict__ indeg, int E) {
    int e = blockIdx.x * blockDim.x + threadIdx.x;
    if (e < E) atomicAdd(&indeg[dst[e]], 1);
}
__global__ void k_dinv(const int* __restrict__ indeg, float* __restrict__ dinv, int n) {
    int i = blockIdx.x * blockDim.x + threadIdx.x;
    if (i < n) dinv[i] = rsqrtf(1.0f + (float)indeg[i]);
}

// ---------------- single-block exclusive scan (shuffle-based) ----------------
__global__ void k_scan(const int* __restrict__ indeg, int* __restrict__ off, int n) {
    __shared__ int wsum[32];
    __shared__ int carry_s;
    int tid = threadIdx.x, lane = tid & 31, wid = tid >> 5;
    if (tid == 0) carry_s = 0;
    __syncthreads();
    for (int base = 0; base < n; base += 1024) {
        int idx = base + tid;
        int v = (idx < n) ? indeg[idx] : 0;
        int incl = v;
        #pragma unroll
        for (int d = 1; d < 32; d <<= 1) {
            int t = __shfl_up_sync(0xffffffffu, incl, d);
            if (lane >= d) incl += t;
        }
        if (lane == 31) wsum[wid] = incl;
        __syncthreads();
        if (wid == 0) {
            int w = wsum[lane];
            #pragma unroll
            for (int d = 1; d < 32; d <<= 1) {
                int t = __shfl_up_sync(0xffffffffu, w, d);
                if (lane >= d) w += t;
            }
            wsum[lane] = w;
        }
        __syncthreads();
        int warpoff = (wid == 0) ? 0 : wsum[wid - 1];
        int carry = carry_s;
        if (idx < n) off[idx] = carry + warpoff + incl - v;
        int total = wsum[31];
        __syncthreads();
        if (tid == 0) carry_s = carry + total;
        __syncthreads();
    }
    if (threadIdx.x == 0) off[n] = carry_s;
}

// ---------------- CSR fill (edge -> slot under its dst row) ----------------
__global__ void k_fill(const int* __restrict__ src, const int* __restrict__ dst,
                       const float* __restrict__ dinv, const int* __restrict__ off,
                       int* __restrict__ cursor, int* __restrict__ csrc,
                       float* __restrict__ cnorm, int E) {
    int e = blockIdx.x * blockDim.x + threadIdx.x;
    if (e >= E) return;
    int s = src[e], d = dst[e];
    int p = off[d] + atomicAdd(&cursor[d], 1);
    csrc[p] = s;
    cnorm[p] = dinv[s] * dinv[d];
}

// ---------------- t = act(h) @ W, 8 rows x one float4-chunk per thread ----------------
template <int KIN, int KOUT4, int RELU>
__global__ void __launch_bounds__(256) k_mm(const float* __restrict__ h,
                                            const float* __restrict__ W,
                                            float* __restrict__ t, int n) {
    const int R = 8;
    int gid = blockIdx.x * 256 + threadIdx.x;
    int c4 = gid % KOUT4;
    int rb = gid / KOUT4;
    int row0 = rb * R;
    if (row0 >= n) return;

    const ulonglong2* Wv = (const ulonglong2*)W;
    unsigned long long acc0[R], acc1[R];
    #pragma unroll
    for (int r = 0; r < R; r++) { acc0[r] = 0ull; acc1[r] = 0ull; }

    const float4* hp[R];
    #pragma unroll
    for (int r = 0; r < R; r++) {
        int rr = row0 + r; if (rr > n - 1) rr = n - 1;
        hp[r] = (const float4*)(h + (size_t)rr * KIN);
    }

    #pragma unroll 2
    for (int k4 = 0; k4 < KIN / 4; k4++) {
        float4 hv[R];
        #pragma unroll
        for (int r = 0; r < R; r++) {
            float4 v = hp[r][k4];
            if (RELU) {
                v.x = fmaxf(v.x, 0.f); v.y = fmaxf(v.y, 0.f);
                v.z = fmaxf(v.z, 0.f); v.w = fmaxf(v.w, 0.f);
            }
            hv[r] = v;
        }
        #pragma unroll
        for (int kk = 0; kk < 4; kk++) {
            ulonglong2 wv = Wv[(k4 * 4 + kk) * KOUT4 + c4];
            #pragma unroll
            for (int r = 0; r < R; r++) {
                float hs = (kk == 0) ? hv[r].x : (kk == 1) ? hv[r].y
                         : (kk == 2) ? hv[r].z : hv[r].w;
                unsigned long long s = splat2(hs);
                acc0[r] = ffma2(s, wv.x, acc0[r]);
                acc1[r] = ffma2(s, wv.y, acc1[r]);
            }
        }
    }
    #pragma unroll
    for (int r = 0; r < R; r++) {
        int rr = row0 + r;
        if (rr < n) {
            ulonglong2 o; o.x = acc0[r]; o.y = acc1[r];
            ((ulonglong2*)t)[(size_t)rr * KOUT4 + c4] = o;
        }
    }
}

// ---------------- aggregation: out[d] = b + t[d]*dinv[d]^2 + sum_in t[s]*norm ----------------
template <int K4>
__global__ void k_aggr(const float* __restrict__ t,
                       const int* __restrict__ csrc, const float* __restrict__ cnorm,
                       const int* __restrict__ off, const float* __restrict__ dinv,
                       const float* __restrict__ bias, float* __restrict__ out, int n) {
    int gid = blockIdx.x * blockDim.x + threadIdx.x;
    int node = gid / K4;
    int c4 = gid % K4;
    if (node >= n) return;
    const float4* t4 = (const float4*)t;
    float d = dinv[node];
    float sl = d * d;
    float4 b4 = ((const float4*)bias)[c4];
    float4 tv = t4[(size_t)node * K4 + c4];
    float4 acc;
    acc.x = fmaf(tv.x, sl, b4.x); acc.y = fmaf(tv.y, sl, b4.y);
    acc.z = fmaf(tv.z, sl, b4.z); acc.w = fmaf(tv.w, sl, b4.w);
    int beg = off[node], end = off[node + 1];
    #pragma unroll 4
    for (int j = beg; j < end; j++) {
        int s = csrc[j];
        float w = cnorm[j];
        float4 v = t4[(size_t)s * K4 + c4];
        acc.x = fmaf(v.x, w, acc.x); acc.y = fmaf(v.y, w, acc.y);
        acc.z = fmaf(v.z, w, acc.z); acc.w = fmaf(v.w, w, acc.w);
    }
    ((float4*)out)[(size_t)node * K4 + c4] = acc;
}

// ---------------- pooling over sorted batch ----------------
__global__ void k_seg_starts(const int* __restrict__ batch, int* __restrict__ start, int n) {
    int i = blockIdx.x * blockDim.x + threadIdx.x;
    if (i >= n) return;
    int b = batch[i];
    if (i == 0 || batch[i - 1] != b) start[b] = i;
}
__global__ void k_pool(const float* __restrict__ h, const int* __restrict__ start,
                       float* __restrict__ pool, int n, int G) {
    int gid = blockIdx.x * blockDim.x + threadIdx.x;
    if (gid >= G * FDIM) return;
    int g = gid / FDIM;
    int j = gid - g * FDIM;
    int beg = start[g];
    int end = (g + 1 < G) ? start[g + 1] : n;
    float m = 0.0f;  // relu(h) >= 0, so 0 is the max identity
    for (int i = beg; i < end; i++)
        m = fmaxf(m, h[(size_t)i * FDIM + j]);
    pool[g * FDIM + j] = m;
}

// ---------------- final heads: 8 graphs per block, 128 threads ----------------
__global__ void k_final(const float* __restrict__ pool, const float* __restrict__ feat,
                        const float* __restrict__ Wg,  const float* __restrict__ bg,
                        const float* __restrict__ Wf1, const float* __restrict__ bf1,
                        const float* __restrict__ Wf2, const float* __restrict__ bf2,
                        float* __restrict__ out, int G) {
    const int GB = 8;
    int g0 = blockIdx.x * GB;
    int j = threadIdx.x;   // 128
    float acc[GB];
    float bj = bf1[j];
    #pragma unroll
    for (int i = 0; i < GB; i++) acc[i] = bj;
    #pragma unroll 2
    for (int k = 0; k < FEATD; k++) {
        float w = Wf1[k * 128 + j];
        #pragma unroll
        for (int i = 0; i < GB; i++) {
            int g = g0 + i;
            float f = (g < G) ? feat[(size_t)g * FEATD + k] : 0.0f;
            acc[i] = fmaf(f, w, acc[i]);
        }
    }
    float wf2 = Wf2[j];
    __shared__ float red[128];
    __shared__ float sums[GB];
    #pragma unroll
    for (int i = 0; i < GB; i++) {
        red[j] = fmaxf(acc[i], 0.0f) * wf2;
        __syncthreads();
        for (int o = 64; o > 0; o >>= 1) {
            if (j < o) red[j] += red[j + o];
            __syncthreads();
        }
        if (j == 0) sums[i] = red[0];
        __syncthreads();
    }
    if (j < GB) {
        int g = g0 + j;
        if (g < G) {
            float a = bg[0];
            #pragma unroll
            for (int k = 0; k < FDIM; k++)
                a = fmaf(pool[g * FDIM + k], Wg[k], a);
            out[g] = fmaxf(a, 0.0f) + sums[j] + bf2[0];
        }
    }
}

// ----------------------------------------------------------------
extern "C" void kernel_launch(void* const* d_in, const int* in_sizes, int n_in,
                              void* d_out, int out_size) {
    const float* x       = (const float*)d_in[0];
    const int*   ei      = (const int*)  d_in[1];
    const int*   batch   = (const int*)  d_in[2];
    const float* feature = (const float*)d_in[3];
    const float* W1 = (const float*)d_in[4];  const float* b1 = (const float*)d_in[5];
    const float* W2 = (const float*)d_in[6];  const float* b2 = (const float*)d_in[7];
    const float* W3 = (const float*)d_in[8];  const float* b3 = (const float*)d_in[9];
    const float* Wg = (const float*)d_in[10]; const float* bg = (const float*)d_in[11];
    const float* Wf1= (const float*)d_in[12]; const float* bf1= (const float*)d_in[13];
    const float* Wf2= (const float*)d_in[14]; const float* bf2= (const float*)d_in[15];

    const int N = in_sizes[2];
    const int E = in_sizes[1] / 2;
    const int G = in_sizes[3] / FEATD;

    float *A, *B, *dinv, *pool, *cnorm;
    int *indeg, *cursor, *off, *csrc, *start;
    cudaGetSymbolAddress((void**)&A,     g_bufA);
    cudaGetSymbolAddress((void**)&B,     g_bufB);
    cudaGetSymbolAddress((void**)&dinv,  g_dinv);
    cudaGetSymbolAddress((void**)&indeg, g_indeg);
    cudaGetSymbolAddress((void**)&cursor,g_cursor);
    cudaGetSymbolAddress((void**)&off,   g_off);
    cudaGetSymbolAddress((void**)&csrc,  g_csrc);
    cudaGetSymbolAddress((void**)&cnorm, g_cnorm);
    cudaGetSymbolAddress((void**)&start, g_start);
    cudaGetSymbolAddress((void**)&pool,  g_pool);

    const int* src = ei;
    const int* dst = ei + E;
    float* out = (float*)d_out;

    const int T = 256;
    auto blocks = [&](int work) { return (work + T - 1) / T; };

    // ---- CSR build + norms ----
    cudaMemsetAsync(indeg, 0, N * sizeof(int));
    cudaMemsetAsync(cursor, 0, N * sizeof(int));
    k_count<<<blocks(E), T>>>(dst, indeg, E);
    k_dinv <<<blocks(N), T>>>(indeg, dinv, N);
    k_scan <<<1, 1024>>>(indeg, off, N);
    k_fill <<<blocks(E), T>>>(src, dst, dinv, off, cursor, csrc, cnorm, E);

    // ---- layer 1: x(44) -> 44 ----
    {
        const int K4 = FDIM / 4;
        int thr = ((N + 7) / 8) * K4;
        k_mm<FDIM, K4, 0><<<blocks(thr), T>>>(x, W1, A, N);
        k_aggr<K4><<<blocks(N * K4), T>>>(A, csrc, cnorm, off, dinv, b1, B, N);
    }
    // ---- layer 2: relu(B)(44) -> 88 ----
    {
        const int K4 = F2DIM / 4;
        int thr = ((N + 7) / 8) * K4;
        k_mm<FDIM, K4, 1><<<blocks(thr), T>>>(B, W2, A, N);
        k_aggr<K4><<<blocks(N * K4), T>>>(A, csrc, cnorm, off, dinv, b2, B, N);
    }
    // ---- layer 3: relu(B)(88) -> 44 ----
    {
        const int K4 = FDIM / 4;
        int thr = ((N + 7) / 8) * K4;
        k_mm<F2DIM, K4, 1><<<blocks(thr), T>>>(B, W3, A, N);
        k_aggr<K4><<<blocks(N * K4), T>>>(A, csrc, cnorm, off, dinv, b3, B, N);
    }

    // ---- pool + heads ----
    k_seg_starts<<<blocks(N), T>>>(batch, start, N);
    k_pool<<<blocks(G * FDIM), T>>>(B, start, pool, N, G);
    k_final<<<(G + 7) / 8, 128>>>(pool, feature, Wg, bg, Wf1, bf1, Wf2, bf2, out, G);
}